// round 2
// baseline (speedup 1.0000x reference)
#include <cuda_runtime.h>

// Global accumulators / flags (no device allocation allowed).
__device__ double g_sum0;              // sum of picked log-probs for class 0
__device__ double g_sum1;              // sum of picked log-probs for class 1
__device__ unsigned long long g_cnt1;  // count of targets == 1
__device__ int g_mode64;               // 1 if targets are stored as int64, 0 if int32

__global__ void init_kernel() {
    g_sum0 = 0.0;
    g_sum1 = 0.0;
    g_cnt1 = 0ull;
    g_mode64 = 1;
}

// Probe the targets buffer interpreted as int32 words.
// If targets are int64 values in {0,1}, every odd word (high half) is 0.
// If targets are int32, odd words are random targets (~50% ones).
// Reads only word indices < n_tokens -> in bounds for BOTH layouts.
__global__ void detect_kernel(const int* __restrict__ t32, long long n_tokens) {
    long long i = (long long)blockIdx.x * blockDim.x + threadIdx.x;
    long long idx = 2 * i + 1;
    if (idx < n_tokens && t32[idx] != 0) {
        g_mode64 = 0;
    }
}

__device__ __forceinline__ void proc_token(float x0, float x1, int t,
                                           float& s0, float& s1, int& c1) {
    // picked log-softmax value: x[t] - logsumexp(x0, x1)
    float m   = fmaxf(x0, x1);
    float d   = -fabsf(x0 - x1);
    float lse = m + __logf(1.0f + __expf(d));
    if (t != 0) {
        s1 += x1 - lse;
        c1 += 1;
    } else {
        s0 += x0 - lse;
    }
}

// Each thread handles 8 tokens: 4x float4 for x; targets via int4 (int32 mode)
// or ulonglong2 (int64 mode). All 128-bit loads, front-batched for MLP.
__global__ __launch_bounds__(256) void nll_main_kernel(
    const float* __restrict__ x,
    const void* __restrict__ targets,
    long long n_tokens)
{
    const long long tid  = (long long)blockIdx.x * blockDim.x + threadIdx.x;
    const long long base = tid * 8;   // first token for this thread

    float s0 = 0.0f, s1 = 0.0f;
    int   c1 = 0;

    const bool m64 = (g_mode64 != 0);

    if (base + 7 < n_tokens) {
        const float4* x4 = reinterpret_cast<const float4*>(x) + base / 2;
        float4 a0 = x4[0];
        float4 a1 = x4[1];
        float4 a2 = x4[2];
        float4 a3 = x4[3];

        int t[8];
        if (m64) {
            const ulonglong2* t2 = reinterpret_cast<const ulonglong2*>(targets) + base / 2;
            ulonglong2 b0 = t2[0];
            ulonglong2 b1 = t2[1];
            ulonglong2 b2 = t2[2];
            ulonglong2 b3 = t2[3];
            t[0] = (int)b0.x; t[1] = (int)b0.y;
            t[2] = (int)b1.x; t[3] = (int)b1.y;
            t[4] = (int)b2.x; t[5] = (int)b2.y;
            t[6] = (int)b3.x; t[7] = (int)b3.y;
        } else {
            const int4* t4 = reinterpret_cast<const int4*>(targets) + base / 4;
            int4 b0 = t4[0];
            int4 b1 = t4[1];
            t[0] = b0.x; t[1] = b0.y; t[2] = b0.z; t[3] = b0.w;
            t[4] = b1.x; t[5] = b1.y; t[6] = b1.z; t[7] = b1.w;
        }

        proc_token(a0.x, a0.y, t[0], s0, s1, c1);
        proc_token(a0.z, a0.w, t[1], s0, s1, c1);
        proc_token(a1.x, a1.y, t[2], s0, s1, c1);
        proc_token(a1.z, a1.w, t[3], s0, s1, c1);
        proc_token(a2.x, a2.y, t[4], s0, s1, c1);
        proc_token(a2.z, a2.w, t[5], s0, s1, c1);
        proc_token(a3.x, a3.y, t[6], s0, s1, c1);
        proc_token(a3.z, a3.w, t[7], s0, s1, c1);
    } else {
        // tail (only hit if n_tokens % 8 != 0)
        for (long long i = base; i < n_tokens && i < base + 8; i++) {
            int ti;
            if (m64) ti = (int)reinterpret_cast<const long long*>(targets)[i];
            else     ti = reinterpret_cast<const int*>(targets)[i];
            proc_token(x[2 * i], x[2 * i + 1], ti, s0, s1, c1);
        }
    }

    // warp reduction
    #pragma unroll
    for (int off = 16; off > 0; off >>= 1) {
        s0 += __shfl_down_sync(0xFFFFFFFFu, s0, off);
        s1 += __shfl_down_sync(0xFFFFFFFFu, s1, off);
        c1 += __shfl_down_sync(0xFFFFFFFFu, c1, off);
    }

    __shared__ float sh0[8];
    __shared__ float sh1[8];
    __shared__ int   shc[8];
    const int lane = threadIdx.x & 31;
    const int wid  = threadIdx.x >> 5;
    if (lane == 0) { sh0[wid] = s0; sh1[wid] = s1; shc[wid] = c1; }
    __syncthreads();

    if (wid == 0) {
        const int nw = blockDim.x >> 5;
        s0 = (lane < nw) ? sh0[lane] : 0.0f;
        s1 = (lane < nw) ? sh1[lane] : 0.0f;
        c1 = (lane < nw) ? shc[lane] : 0;
        #pragma unroll
        for (int off = 4; off > 0; off >>= 1) {
            s0 += __shfl_down_sync(0xFFFFFFFFu, s0, off);
            s1 += __shfl_down_sync(0xFFFFFFFFu, s1, off);
            c1 += __shfl_down_sync(0xFFFFFFFFu, c1, off);
        }
        if (lane == 0) {
            atomicAdd(&g_sum0, (double)s0);
            atomicAdd(&g_sum1, (double)s1);
            atomicAdd(&g_cnt1, (unsigned long long)c1);
        }
    }
}

__global__ void finalize_kernel(float* __restrict__ out, long long n_tokens) {
    unsigned long long n1 = g_cnt1;
    unsigned long long n0 = (unsigned long long)n_tokens - n1;
    double r = (n1 > 0) ? (-g_sum1 / (double)n1) : 0.0;
    double p = (n0 > 0) ? (-g_sum0 / (double)n0) : 0.0;
    out[0] = (float)(p + r);
}

extern "C" void kernel_launch(void* const* d_in, const int* in_sizes, int n_in,
                              void* d_out, int out_size) {
    const float* x       = (const float*)d_in[0];
    const void*  targets = d_in[1];
    float*       out     = (float*)d_out;

    const long long n_tokens = (long long)in_sizes[1];

    init_kernel<<<1, 1>>>();

    // Probe 4096 odd word positions (indices up to 8191 < n_tokens).
    detect_kernel<<<4, 1024>>>((const int*)targets, n_tokens);

    const long long threads_needed = (n_tokens + 7) / 8;
    const int block = 256;
    const int grid  = (int)((threads_needed + block - 1) / block);
    nll_main_kernel<<<grid, block>>>(x, targets, n_tokens);

    finalize_kernel<<<1, 1>>>(out, n_tokens);
}